// round 5
// baseline (speedup 1.0000x reference)
#include <cuda_runtime.h>
#include <cstdint>

// Problem constants (fixed shapes for this problem instance)
#define NODES   50000
#define EDGES   800000
#define INF     512
#define OUTF    512
#define HEADS   8
#define NBASES  4
#define FHD     64          // OUTF/HEADS
#define AGGC    256         // NBASES*FHD
#define WCOMB   32          // HEADS*NBASES
#define NCAT    800         // 256 + 32 + 512 concatenated GEMM output cols
#define LNEPS   1e-5f

// ---------- device scratch (static allocation; no cudaMalloc allowed) ----------
__device__ float g_wcat[INF * NCAT];                 // concatenated weights [512,800]
__device__ float g_cat[(size_t)NODES * NCAT];        // x @ Wcat  [N,800]  (~160MB)
__device__ float g_agg[(size_t)NODES * AGGC];        // symnorm aggregation [N,256] (~51MB)
__device__ float g_dinv[NODES];
__device__ int   g_deg[NODES];

// ---------- zero agg + deg ----------
__global__ void zero_kernel(int nAgg4, int nDeg) {
    int i = blockIdx.x * blockDim.x + threadIdx.x;
    if (i < nAgg4) reinterpret_cast<float4*>(g_agg)[i] = make_float4(0.f, 0.f, 0.f, 0.f);
    if (i < nDeg)  g_deg[i] = 0;
}

// ---------- concat weights into g_wcat ----------
__global__ void concatw_kernel(const float* __restrict__ Wb,
                               const float* __restrict__ Wc,
                               const float* __restrict__ Wr) {
    int i = blockIdx.x * blockDim.x + threadIdx.x;
    if (i >= INF * NCAT) return;
    int k = i / NCAT, c = i - k * NCAT;
    float v;
    if (c < AGGC)             v = Wb[k * AGGC + c];
    else if (c < AGGC + WCOMB) v = Wc[k * WCOMB + (c - AGGC)];
    else                       v = Wr[k * OUTF + (c - AGGC - WCOMB)];
    g_wcat[i] = v;
}

// ---------- degree count (dst occurrences) ----------
__global__ void deg_kernel(const int* __restrict__ ei, int E) {
    int i = blockIdx.x * blockDim.x + threadIdx.x;
    if (i < E) atomicAdd(&g_deg[ei[E + i]], 1);
}

__global__ void dinv_kernel(int n) {
    int i = blockIdx.x * blockDim.x + threadIdx.x;
    if (i < n) g_dinv[i] = rsqrtf((float)(g_deg[i] + 1));  // +1 self loop
}

// ---------- TF32 tensor-core GEMM: g_cat[M,800] = x[M,512] @ g_wcat[512,800] ----------
// 128x128 block tile, BK=32, 256 threads (8 warps: 4m x 2n), warp tile 32x64.
// k interleaved in 8-groups [0,4,1,5,2,6,3,7] in SMEM (same perm for A and B ->
// dot product unchanged) so fragment (lc, lc+4) pairs are LDS.64.
// Row stride 40 words => frag-load banks 8*lr+2*lc, conflict-free.
__device__ __forceinline__ uint32_t f2tf32(float f) {
    uint32_t u;
    asm("cvt.rna.tf32.f32 %0, %1;" : "=r"(u) : "f"(f));
    return u;
}

__device__ __forceinline__ void mma_tf32(float* d, const uint32_t* a, const uint32_t* b) {
    asm volatile("mma.sync.aligned.m16n8k8.row.col.f32.tf32.tf32.f32 "
                 "{%0,%1,%2,%3},{%4,%5,%6,%7},{%8,%9},{%0,%1,%2,%3};"
                 : "+f"(d[0]), "+f"(d[1]), "+f"(d[2]), "+f"(d[3])
                 : "r"(a[0]), "r"(a[1]), "r"(a[2]), "r"(a[3]),
                   "r"(b[0]), "r"(b[1]));
}

#define GBM 128
#define GBN 128
#define GBK 32
#define SPITCH 40   // row stride (words); 40 mod 32 == 8 -> conflict-free frag LDS.64

__global__ __launch_bounds__(256, 2)
void tf32gemm_kernel(const float* __restrict__ A, int M) {
    __shared__ uint32_t As[GBM][SPITCH];   // [m][k_interleaved]
    __shared__ uint32_t Bs[GBN][SPITCH];   // [n][k_interleaved]
    const int t    = threadIdx.x;
    const int wid  = t >> 5;
    const int lane = t & 31;
    const int wm   = wid & 3;          // 0..3 -> 32-row stripes
    const int wn   = wid >> 2;         // 0..1 -> 64-col stripes
    const int lr   = lane >> 2;        // groupID (0..7)
    const int lc   = lane & 3;         // threadID_in_group (0..3)
    const int m0   = blockIdx.y * GBM;
    const int n0   = blockIdx.x * GBN;

    float acc[2][8][4];
#pragma unroll
    for (int mt = 0; mt < 2; mt++)
#pragma unroll
        for (int nt = 0; nt < 8; nt++)
#pragma unroll
            for (int r = 0; r < 4; r++) acc[mt][nt][r] = 0.f;

    float4 pa[4];   // A prefetch: 128 rows x 32 k = 1024 float4 / 256 thr
    float4 pb[4];   // B prefetch: 32 k x 128 n  = 1024 float4 / 256 thr

    auto loadA = [&](int kt) {
#pragma unroll
        for (int i = 0; i < 4; i++) {
            int f   = t + i * 256;
            int row = f >> 3;            // 0..127
            int cq  = (f & 7) * 4;       // k base 0..28
            int gr  = m0 + row;
            pa[i] = (gr < M)
                  ? *reinterpret_cast<const float4*>(A + (size_t)gr * INF + kt + cq)
                  : make_float4(0.f, 0.f, 0.f, 0.f);
        }
    };
    auto loadB = [&](int kt) {
#pragma unroll
        for (int i = 0; i < 4; i++) {
            int f   = t + i * 256;
            int kr  = f >> 5;            // 0..31
            int cq  = (f & 31) * 4;      // col base 0..124
            int gc  = n0 + cq;
            pb[i] = (gc < NCAT)
                  ? *reinterpret_cast<const float4*>(g_wcat + (size_t)(kt + kr) * NCAT + gc)
                  : make_float4(0.f, 0.f, 0.f, 0.f);
        }
    };

    loadA(0);
    loadB(0);

    for (int kt = 0; kt < INF; kt += GBK) {
        // ---- stage prefetch -> smem with tf32 convert + k-interleave ----
        // A: element k = cq+e -> phys p = (cq&24) + 2e + ((cq&4)?1:0)
#pragma unroll
        for (int i = 0; i < 4; i++) {
            int f   = t + i * 256;
            int row = f >> 3;
            int cq  = (f & 7) * 4;
            int pbase = (cq & 24) + ((cq & 4) ? 1 : 0);
            float v[4] = {pa[i].x, pa[i].y, pa[i].z, pa[i].w};
#pragma unroll
            for (int e = 0; e < 4; e++)
                As[row][pbase + 2 * e] = f2tf32(v[e]);
        }
        // B: row kr -> phys pk = (kr&24) + 2*(kr&3) + ((kr&4)?1:0); cols cq..cq+3
#pragma unroll
        for (int i = 0; i < 4; i++) {
            int f   = t + i * 256;
            int kr  = f >> 5;
            int cq  = (f & 31) * 4;
            int pk  = (kr & 24) + 2 * (kr & 3) + ((kr & 4) ? 1 : 0);
            float v[4] = {pb[i].x, pb[i].y, pb[i].z, pb[i].w};
#pragma unroll
            for (int e = 0; e < 4; e++)
                Bs[cq + e][pk] = f2tf32(v[e]);
        }
        __syncthreads();

        if (kt + GBK < INF) {
            loadA(kt + GBK);
            loadB(kt + GBK);
        }

        // ---- compute: 4 k-groups of 8 ----
#pragma unroll
        for (int kc = 0; kc < 4; kc++) {
            const int ko = kc * 8 + 2 * lc;
            uint32_t af[2][4];
#pragma unroll
            for (int mt = 0; mt < 2; mt++) {
                int r0 = wm * 32 + mt * 16 + lr;
                uint2 lo = *reinterpret_cast<const uint2*>(&As[r0][ko]);
                uint2 hi = *reinterpret_cast<const uint2*>(&As[r0 + 8][ko]);
                af[mt][0] = lo.x;  // a0 = A[lr][lc]
                af[mt][1] = hi.x;  // a1 = A[lr+8][lc]
                af[mt][2] = lo.y;  // a2 = A[lr][lc+4]
                af[mt][3] = hi.y;  // a3 = A[lr+8][lc+4]
            }
#pragma unroll
            for (int nt = 0; nt < 8; nt++) {
                int col = wn * 64 + nt * 8 + lr;
                uint2 bb = *reinterpret_cast<const uint2*>(&Bs[col][ko]);
                uint32_t bf[2] = {bb.x, bb.y};
#pragma unroll
                for (int mt = 0; mt < 2; mt++)
                    mma_tf32(acc[mt][nt], af[mt], bf);
            }
        }
        __syncthreads();
    }

    // store: c0,c1 at (row, col..col+1); c2,c3 at (row+8, ...)
#pragma unroll
    for (int mt = 0; mt < 2; mt++) {
#pragma unroll
        for (int nt = 0; nt < 8; nt++) {
            int row = m0 + wm * 32 + mt * 16 + lr;
            int col = n0 + wn * 64 + nt * 8 + 2 * lc;
            if (col < NCAT) {
                if (row < M) {
                    float2 v = make_float2(acc[mt][nt][0], acc[mt][nt][1]);
                    *reinterpret_cast<float2*>(g_cat + (size_t)row * NCAT + col) = v;
                }
                if (row + 8 < M) {
                    float2 v = make_float2(acc[mt][nt][2], acc[mt][nt][3]);
                    *reinterpret_cast<float2*>(g_cat + (size_t)(row + 8) * NCAT + col) = v;
                }
            }
        }
    }
}

// ---------- edge scatter: agg[dst] += bases[src] * dinv[src]*dinv[dst] ----------
__device__ __forceinline__ void red_add_v4(float* addr, float a, float b, float c, float d) {
    asm volatile("red.global.add.v4.f32 [%0], {%1, %2, %3, %4};"
                 :: "l"(addr), "f"(a), "f"(b), "f"(c), "f"(d) : "memory");
}

__global__ void scatter_kernel(const int* __restrict__ ei, int E) {
    int w = (blockIdx.x * blockDim.x + threadIdx.x) >> 5;
    if (w >= E) return;
    int lane = threadIdx.x & 31;
    int src = __ldg(ei + w);
    int dst = __ldg(ei + E + w);
    float nrm = __ldg(g_dinv + src) * __ldg(g_dinv + dst);
    const float4* brow = reinterpret_cast<const float4*>(g_cat + (size_t)src * NCAT);
    float* arow = g_agg + (size_t)dst * AGGC;
#pragma unroll
    for (int i = 0; i < 2; i++) {
        int q = lane + i * 32;
        float4 v = __ldg(brow + q);
        red_add_v4(arow + q * 4, v.x * nrm, v.y * nrm, v.z * nrm, v.w * nrm);
    }
}

// ---------- combine: einsum + biases + residual + LayerNorm + ReLU ----------
__global__ __launch_bounds__(128)
void combine_kernel(const float* __restrict__ b_comb,
                    const float* __restrict__ conv_bias,
                    const float* __restrict__ b_res,
                    const float* __restrict__ gamma,
                    const float* __restrict__ beta,
                    float* __restrict__ out) {
    int v = blockIdx.x;
    int tid = threadIdx.x;
    __shared__ float sagg[AGGC];
    __shared__ float sw[WCOMB];
    __shared__ float red[8];

    float d = g_dinv[v];
    float d2 = d * d;
    const float* oc = g_cat + (size_t)v * NCAT;
    const float* ag = g_agg + (size_t)v * AGGC;

    // agg row + self-loop term
#pragma unroll
    for (int j = 0; j < 2; j++) {
        int i = tid + j * 128;
        sagg[i] = ag[i] + oc[i] * d2;
    }
    if (tid < WCOMB) sw[tid] = oc[AGGC + tid] + b_comb[tid];
    __syncthreads();

    float val[4];
    float s = 0.f, sq = 0.f;
#pragma unroll
    for (int j = 0; j < 4; j++) {
        int c = tid + j * 128;
        int h = c >> 6, f = c & 63;
        const float* wv = &sw[h * 4];
        float a = wv[0] * sagg[f]
                + wv[1] * sagg[64 + f]
                + wv[2] * sagg[128 + f]
                + wv[3] * sagg[192 + f];
        a += conv_bias[c] + oc[AGGC + WCOMB + c] + b_res[c];
        val[j] = a;
        s += a;
        sq += a * a;
    }
    // block reduce (4 warps)
#pragma unroll
    for (int o = 16; o > 0; o >>= 1) {
        s  += __shfl_xor_sync(0xffffffffu, s, o);
        sq += __shfl_xor_sync(0xffffffffu, sq, o);
    }
    if ((tid & 31) == 0) { red[tid >> 5] = s; red[4 + (tid >> 5)] = sq; }
    __syncthreads();
    s  = red[0] + red[1] + red[2] + red[3];
    sq = red[4] + red[5] + red[6] + red[7];
    float mean = s * (1.f / OUTF);
    float var  = sq * (1.f / OUTF) - mean * mean;
    float rstd = rsqrtf(var + LNEPS);
#pragma unroll
    for (int j = 0; j < 4; j++) {
        int c = tid + j * 128;
        float o = (val[j] - mean) * rstd * gamma[c] + beta[c];
        out[(size_t)v * OUTF + c] = fmaxf(o, 0.f);
    }
}

extern "C" void kernel_launch(void* const* d_in, const int* in_sizes, int n_in,
                              void* d_out, int out_size) {
    const float* x     = (const float*)d_in[0];
    const int*   ei    = (const int*)  d_in[1];
    const float* Wb    = (const float*)d_in[2];
    const float* Wc    = (const float*)d_in[3];
    const float* bcomb = (const float*)d_in[4];
    const float* cbias = (const float*)d_in[5];
    const float* Wr    = (const float*)d_in[6];
    const float* bres  = (const float*)d_in[7];
    const float* gamma = (const float*)d_in[8];
    const float* beta  = (const float*)d_in[9];
    float* out = (float*)d_out;

    const int N = in_sizes[0] / INF;
    const int E = in_sizes[1] / 2;

    // 1. zero agg + deg
    {
        int nAgg4 = (N * AGGC) / 4;
        int blocks = (nAgg4 + 255) / 256;
        zero_kernel<<<blocks, 256>>>(nAgg4, N);
    }
    // 2. concat weights
    concatw_kernel<<<(INF * NCAT + 255) / 256, 256>>>(Wb, Wc, Wr);
    // 3. degrees
    deg_kernel<<<(E + 255) / 256, 256>>>(ei, E);
    dinv_kernel<<<(N + 255) / 256, 256>>>(N);
    // 4. fused GEMM (TF32 tensor cores): g_cat = x @ g_wcat
    {
        dim3 grid((NCAT + GBN - 1) / GBN, (N + GBM - 1) / GBM);
        tf32gemm_kernel<<<grid, 256>>>(x, N);
    }
    // 5. edge scatter with vectorized reduction atomics
    {
        long long threads = (long long)E * 32;
        int blocks = (int)((threads + 255) / 256);
        scatter_kernel<<<blocks, 256>>>(ei, E);
    }
    // 6. combine + LayerNorm + ReLU
    combine_kernel<<<N, 128>>>(bcomb, cbias, bres, gamma, beta, out);
}

// round 6
// speedup vs baseline: 2.6567x; 2.6567x over previous
#include <cuda_runtime.h>
#include <cuda_fp16.h>
#include <cstdint>

// Problem constants (fixed shapes for this problem instance)
#define NODES   50000
#define EDGES   800000
#define INF     512
#define OUTF    512
#define HEADS   8
#define NBASES  4
#define FHD     64          // OUTF/HEADS
#define AGGC    256         // NBASES*FHD
#define WCOMB   32          // HEADS*NBASES
#define NCAT    800         // 256 + 32 + 512 concatenated GEMM output cols
#define LNEPS   1e-5f

// ---------- device scratch (static allocation; no cudaMalloc allowed) ----------
__device__ float g_wcatT[(size_t)NCAT * INF];        // transposed concat weights [800,512]
__device__ float g_cat[(size_t)NODES * NCAT];        // x @ Wcat  [N,800]  (~160MB)
__device__ float g_agg[(size_t)NODES * AGGC];        // symnorm aggregation [N,256] (~51MB)
__device__ float g_dinv[NODES];
__device__ int   g_deg[NODES];

// ---------- zero agg + deg ----------
__global__ void zero_kernel(int nAgg4, int nDeg) {
    int i = blockIdx.x * blockDim.x + threadIdx.x;
    if (i < nAgg4) reinterpret_cast<float4*>(g_agg)[i] = make_float4(0.f, 0.f, 0.f, 0.f);
    if (i < nDeg)  g_deg[i] = 0;
}

// ---------- concat + transpose weights into g_wcatT[c][k] ----------
__global__ void concatw_kernel(const float* __restrict__ Wb,
                               const float* __restrict__ Wc,
                               const float* __restrict__ Wr) {
    int i = blockIdx.x * blockDim.x + threadIdx.x;
    if (i >= INF * NCAT) return;
    int k = i & (INF - 1);       // fastest -> coalesced writes
    int c = i >> 9;
    float v;
    if (c < AGGC)              v = Wb[k * AGGC + c];
    else if (c < AGGC + WCOMB) v = Wc[k * WCOMB + (c - AGGC)];
    else                       v = Wr[k * OUTF + (c - AGGC - WCOMB)];
    g_wcatT[(size_t)c * INF + k] = v;
}

// ---------- degree count (dst occurrences) ----------
__global__ void deg_kernel(const int* __restrict__ ei, int E) {
    int i = blockIdx.x * blockDim.x + threadIdx.x;
    if (i < E) atomicAdd(&g_deg[ei[E + i]], 1);
}

__global__ void dinv_kernel(int n) {
    int i = blockIdx.x * blockDim.x + threadIdx.x;
    if (i < n) g_dinv[i] = rsqrtf((float)(g_deg[i] + 1));  // +1 self loop
}

// ---------- FP16 tensor-core GEMM: g_cat[M,800] = x[M,512] @ W[512,800] ----------
// 128x128 block tile, BK=32 (16 half2), 256 threads (8 warps 4m x 2n), warp 32x64.
// Both operands stored [row][kpair] as half2, pitch 20 words:
// fragment banks (20*lr + lc) mod 32 all-distinct -> conflict-free scalar LDS.
__device__ __forceinline__ void mma_f16(float* d, const uint32_t* a, const uint32_t* b) {
    asm volatile("mma.sync.aligned.m16n8k16.row.col.f32.f16.f16.f32 "
                 "{%0,%1,%2,%3},{%4,%5,%6,%7},{%8,%9},{%0,%1,%2,%3};"
                 : "+f"(d[0]), "+f"(d[1]), "+f"(d[2]), "+f"(d[3])
                 : "r"(a[0]), "r"(a[1]), "r"(a[2]), "r"(a[3]),
                   "r"(b[0]), "r"(b[1]));
}

__device__ __forceinline__ uint32_t pack_h2(float lo, float hi) {
    __half2 h = __floats2half2_rn(lo, hi);
    return *reinterpret_cast<uint32_t*>(&h);
}

#define GBM 128
#define GBN 128
#define GBK 32
#define HP  20    // row pitch in words (16 half2 used + 4 pad)

__global__ __launch_bounds__(256, 2)
void f16gemm_kernel(const float* __restrict__ A, int M) {
    __shared__ uint32_t As[GBM][HP];   // [m][kpair]
    __shared__ uint32_t Bs[GBN][HP];   // [n][kpair]
    const int t    = threadIdx.x;
    const int wid  = t >> 5;
    const int lane = t & 31;
    const int wm   = wid & 3;          // 0..3 -> 32-row stripes
    const int wn   = wid >> 2;         // 0..1 -> 64-col stripes
    const int lr   = lane >> 2;        // groupID (0..7)
    const int lc   = lane & 3;         // threadID_in_group (0..3)
    const int m0   = blockIdx.y * GBM;
    const int n0   = blockIdx.x * GBN;

    float acc[2][8][4];
#pragma unroll
    for (int mt = 0; mt < 2; mt++)
#pragma unroll
        for (int nt = 0; nt < 8; nt++)
#pragma unroll
            for (int r = 0; r < 4; r++) acc[mt][nt][r] = 0.f;

    // prefetch regs: each thread covers 2 uint4 slots per operand,
    // each slot needs 8 consecutive k floats = 2 float4
    float4 pa[2][2], pb[2][2];

    auto loadA = [&](int kt) {
#pragma unroll
        for (int i = 0; i < 2; i++) {
            int f   = t + i * 256;       // 0..511
            int row = f >> 2;            // 0..127
            int q4  = (f & 3) * 4;       // half2 slot base 0,4,8,12
            int gr  = m0 + row;
            const float* src = A + (size_t)gr * INF + kt + q4 * 2;
            if (gr < M) {
                pa[i][0] = *reinterpret_cast<const float4*>(src);
                pa[i][1] = *reinterpret_cast<const float4*>(src + 4);
            } else {
                pa[i][0] = pa[i][1] = make_float4(0.f, 0.f, 0.f, 0.f);
            }
        }
    };
    auto loadB = [&](int kt) {
#pragma unroll
        for (int i = 0; i < 2; i++) {
            int f   = t + i * 256;
            int row = f >> 2;
            int q4  = (f & 3) * 4;
            int gn  = n0 + row;
            const float* src = g_wcatT + (size_t)gn * INF + kt + q4 * 2;
            if (gn < NCAT) {
                pb[i][0] = *reinterpret_cast<const float4*>(src);
                pb[i][1] = *reinterpret_cast<const float4*>(src + 4);
            } else {
                pb[i][0] = pb[i][1] = make_float4(0.f, 0.f, 0.f, 0.f);
            }
        }
    };

    loadA(0);
    loadB(0);

    for (int kt = 0; kt < INF; kt += GBK) {
        // stage prefetch -> smem (fp16 pack, STS.128)
#pragma unroll
        for (int i = 0; i < 2; i++) {
            int f   = t + i * 256;
            int row = f >> 2;
            int q4  = (f & 3) * 4;
            uint4 ua = make_uint4(pack_h2(pa[i][0].x, pa[i][0].y),
                                  pack_h2(pa[i][0].z, pa[i][0].w),
                                  pack_h2(pa[i][1].x, pa[i][1].y),
                                  pack_h2(pa[i][1].z, pa[i][1].w));
            *reinterpret_cast<uint4*>(&As[row][q4]) = ua;
            uint4 ub = make_uint4(pack_h2(pb[i][0].x, pb[i][0].y),
                                  pack_h2(pb[i][0].z, pb[i][0].w),
                                  pack_h2(pb[i][1].x, pb[i][1].y),
                                  pack_h2(pb[i][1].z, pb[i][1].w));
            *reinterpret_cast<uint4*>(&Bs[row][q4]) = ub;
        }
        __syncthreads();

        if (kt + GBK < INF) {
            loadA(kt + GBK);
            loadB(kt + GBK);
        }

        // compute: 2 k16 steps per slab
#pragma unroll
        for (int s = 0; s < 2; s++) {
            const int ko = s * 8;
            uint32_t af[2][4];
#pragma unroll
            for (int mt = 0; mt < 2; mt++) {
                int r0 = wm * 32 + mt * 16 + lr;
                af[mt][0] = As[r0][ko + lc];
                af[mt][1] = As[r0 + 8][ko + lc];
                af[mt][2] = As[r0][ko + lc + 4];
                af[mt][3] = As[r0 + 8][ko + lc + 4];
            }
#pragma unroll
            for (int nt = 0; nt < 8; nt++) {
                int col = wn * 64 + nt * 8 + lr;
                uint32_t bf[2];
                bf[0] = Bs[col][ko + lc];
                bf[1] = Bs[col][ko + lc + 4];
#pragma unroll
                for (int mt = 0; mt < 2; mt++)
                    mma_f16(acc[mt][nt], af[mt], bf);
            }
        }
        __syncthreads();
    }

    // store: c0,c1 at (row, col..col+1); c2,c3 at (row+8, ...)
#pragma unroll
    for (int mt = 0; mt < 2; mt++) {
#pragma unroll
        for (int nt = 0; nt < 8; nt++) {
            int row = m0 + wm * 32 + mt * 16 + lr;
            int col = n0 + wn * 64 + nt * 8 + 2 * lc;
            if (col < NCAT) {
                if (row < M) {
                    float2 v = make_float2(acc[mt][nt][0], acc[mt][nt][1]);
                    *reinterpret_cast<float2*>(g_cat + (size_t)row * NCAT + col) = v;
                }
                if (row + 8 < M) {
                    float2 v = make_float2(acc[mt][nt][2], acc[mt][nt][3]);
                    *reinterpret_cast<float2*>(g_cat + (size_t)(row + 8) * NCAT + col) = v;
                }
            }
        }
    }
}

// ---------- edge scatter: agg[dst] += bases[src] * dinv[src]*dinv[dst] ----------
__device__ __forceinline__ void red_add_v4(float* addr, float a, float b, float c, float d) {
    asm volatile("red.global.add.v4.f32 [%0], {%1, %2, %3, %4};"
                 :: "l"(addr), "f"(a), "f"(b), "f"(c), "f"(d) : "memory");
}

__global__ void scatter_kernel(const int* __restrict__ ei, int E) {
    int w = (blockIdx.x * blockDim.x + threadIdx.x) >> 5;
    if (w >= E) return;
    int lane = threadIdx.x & 31;
    int src = __ldg(ei + w);
    int dst = __ldg(ei + E + w);
    float nrm = __ldg(g_dinv + src) * __ldg(g_dinv + dst);
    const float4* brow = reinterpret_cast<const float4*>(g_cat + (size_t)src * NCAT);
    float* arow = g_agg + (size_t)dst * AGGC;
#pragma unroll
    for (int i = 0; i < 2; i++) {
        int q = lane + i * 32;
        float4 v = __ldg(brow + q);
        red_add_v4(arow + q * 4, v.x * nrm, v.y * nrm, v.z * nrm, v.w * nrm);
    }
}

// ---------- combine: einsum + biases + residual + LayerNorm + ReLU ----------
__global__ __launch_bounds__(128)
void combine_kernel(const float* __restrict__ b_comb,
                    const float* __restrict__ conv_bias,
                    const float* __restrict__ b_res,
                    const float* __restrict__ gamma,
                    const float* __restrict__ beta,
                    float* __restrict__ out) {
    int v = blockIdx.x;
    int tid = threadIdx.x;
    __shared__ float sagg[AGGC];
    __shared__ float sw[WCOMB];
    __shared__ float red[8];

    float d = g_dinv[v];
    float d2 = d * d;
    const float* oc = g_cat + (size_t)v * NCAT;
    const float* ag = g_agg + (size_t)v * AGGC;

    // agg row + self-loop term
#pragma unroll
    for (int j = 0; j < 2; j++) {
        int i = tid + j * 128;
        sagg[i] = ag[i] + oc[i] * d2;
    }
    if (tid < WCOMB) sw[tid] = oc[AGGC + tid] + b_comb[tid];
    __syncthreads();

    float val[4];
    float s = 0.f, sq = 0.f;
#pragma unroll
    for (int j = 0; j < 4; j++) {
        int c = tid + j * 128;
        int h = c >> 6, f = c & 63;
        const float* wv = &sw[h * 4];
        float a = wv[0] * sagg[f]
                + wv[1] * sagg[64 + f]
                + wv[2] * sagg[128 + f]
                + wv[3] * sagg[192 + f];
        a += conv_bias[c] + oc[AGGC + WCOMB + c] + b_res[c];
        val[j] = a;
        s += a;
        sq += a * a;
    }
    // block reduce (4 warps)
#pragma unroll
    for (int o = 16; o > 0; o >>= 1) {
        s  += __shfl_xor_sync(0xffffffffu, s, o);
        sq += __shfl_xor_sync(0xffffffffu, sq, o);
    }
    if ((tid & 31) == 0) { red[tid >> 5] = s; red[4 + (tid >> 5)] = sq; }
    __syncthreads();
    s  = red[0] + red[1] + red[2] + red[3];
    sq = red[4] + red[5] + red[6] + red[7];
    float mean = s * (1.f / OUTF);
    float var  = sq * (1.f / OUTF) - mean * mean;
    float rstd = rsqrtf(var + LNEPS);
#pragma unroll
    for (int j = 0; j < 4; j++) {
        int c = tid + j * 128;
        float o = (val[j] - mean) * rstd * gamma[c] + beta[c];
        out[(size_t)v * OUTF + c] = fmaxf(o, 0.f);
    }
}

extern "C" void kernel_launch(void* const* d_in, const int* in_sizes, int n_in,
                              void* d_out, int out_size) {
    const float* x     = (const float*)d_in[0];
    const int*   ei    = (const int*)  d_in[1];
    const float* Wb    = (const float*)d_in[2];
    const float* Wc    = (const float*)d_in[3];
    const float* bcomb = (const float*)d_in[4];
    const float* cbias = (const float*)d_in[5];
    const float* Wr    = (const float*)d_in[6];
    const float* bres  = (const float*)d_in[7];
    const float* gamma = (const float*)d_in[8];
    const float* beta  = (const float*)d_in[9];
    float* out = (float*)d_out;

    const int N = in_sizes[0] / INF;
    const int E = in_sizes[1] / 2;

    // 1. zero agg + deg
    {
        int nAgg4 = (N * AGGC) / 4;
        int blocks = (nAgg4 + 255) / 256;
        zero_kernel<<<blocks, 256>>>(nAgg4, N);
    }
    // 2. concat + transpose weights
    concatw_kernel<<<(INF * NCAT + 255) / 256, 256>>>(Wb, Wc, Wr);
    // 3. degrees
    deg_kernel<<<(E + 255) / 256, 256>>>(ei, E);
    dinv_kernel<<<(N + 255) / 256, 256>>>(N);
    // 4. fused GEMM (FP16 tensor cores, fp32 accum): g_cat = x @ W
    {
        dim3 grid((NCAT + GBN - 1) / GBN, (N + GBM - 1) / GBM);
        f16gemm_kernel<<<grid, 256>>>(x, N);
    }
    // 5. edge scatter with vectorized reduction atomics
    {
        long long threads = (long long)E * 32;
        int blocks = (int)((threads + 255) / 256);
        scatter_kernel<<<blocks, 256>>>(ei, E);
    }
    // 6. combine + LayerNorm + ReLU
    combine_kernel<<<N, 128>>>(bcomb, cbias, bres, gamma, beta, out);
}